// round 12
// baseline (speedup 1.0000x reference)
#include <cuda_runtime.h>
#include <cuda_bf16.h>
#include <math.h>
#include <stdint.h>

#define D_IN   256
#define D_EMB  512
#define K_CB   2048
#define T_MAX  65536
#define MARGIN 3.0e-4f
#define NB_EXACT 2048

#define MT   128                 // tokens per CTA
#define FLD  264                 // bf16 pitch (528B rows; 16B aligned; ldmatrix conflict-free)
#define OFF_A0 67584
#define OFF_A1 135168
#define OFF_C  202752
#define OFF_MV 210944            // float [2][128][3]
#define OFF_MI 214016            // int   [2][128][3]
#define K2_SMEM 217088

// ---------------- scratch (device globals; no allocations allowed) -----------
__device__ __align__(16) float g_Q[K_CB * D_IN];
__device__ __align__(16) float g_W1T[D_IN * D_EMB];
__device__ __align__(16) float g_W2T[D_EMB * D_IN];
__device__ __align__(16) __nv_bfloat16 g_Ahi[K_CB * D_IN];  // [cb][i] row-major
__device__ __align__(16) __nv_bfloat16 g_Alo[K_CB * D_IN];
__device__ float g_c[K_CB];
__device__ float g_se[K_CB];
__device__ float g_b1eff[D_EMB];
__device__ int g_idx[T_MAX];
__device__ unsigned int g_hist[K_CB];
__device__ double g_partial[8192];
__device__ int g_ccount[T_MAX];
__device__ unsigned short g_cand[T_MAX][16];
__device__ int g_needy[T_MAX];
__device__ int g_nneedy;

static __device__ __forceinline__ uint32_t smem_u32(const void* p) {
    uint32_t a;
    asm("{ .reg .u64 t; cvta.to.shared.u64 t, %1; cvt.u32.u64 %0, t; }" : "=r"(a) : "l"(p));
    return a;
}
#define CP_COMMIT() asm volatile("cp.async.commit_group;" ::: "memory")
#define CP_WAIT0()  asm volatile("cp.async.wait_group 0;" ::: "memory")

static __device__ __forceinline__ void ldsm_x4(uint32_t* r, uint32_t addr) {
    asm volatile("ldmatrix.sync.aligned.m8n8.x4.shared.b16 {%0,%1,%2,%3}, [%4];"
        : "=r"(r[0]), "=r"(r[1]), "=r"(r[2]), "=r"(r[3]) : "r"(addr));
}
static __device__ __forceinline__ void mma16816(float* d, const uint32_t* a, const uint32_t* b) {
    asm volatile("mma.sync.aligned.m16n8k16.row.col.f32.bf16.bf16.f32 "
        "{%0,%1,%2,%3}, {%4,%5,%6,%7}, {%8,%9}, {%0,%1,%2,%3};"
        : "+f"(d[0]), "+f"(d[1]), "+f"(d[2]), "+f"(d[3])
        : "r"(a[0]), "r"(a[1]), "r"(a[2]), "r"(a[3]), "r"(b[0]), "r"(b[1]));
}

// ---------------- KT: tiled transpose ----------------------------------------
__global__ void kT_transpose(const float* __restrict__ src, float* __restrict__ dst,
                             int R, int C) {
    __shared__ float tile[32][33];
    int bx = blockIdx.x * 32, by = blockIdx.y * 32;
    int x = bx + threadIdx.x;
    int y = by + threadIdx.y;
#pragma unroll
    for (int j = 0; j < 32; j += 8)
        if (y + j < R && x < C) tile[threadIdx.y + j][threadIdx.x] = src[(size_t)(y + j) * C + x];
    __syncthreads();
    x = by + threadIdx.x;
    y = bx + threadIdx.y;
#pragma unroll
    for (int j = 0; j < 32; j += 8)
        if (y + j < C && x < R) dst[(size_t)(y + j) * R + x] = tile[threadIdx.x][threadIdx.y + j];
}

// ---------------- K0 -----------------------------------------------------------
__global__ void k0_init(const float* __restrict__ b1, const float* __restrict__ beta1) {
    int t = blockIdx.x * blockDim.x + threadIdx.x;
    if (t < D_EMB) {
        float s = b1[t];
        for (int i = 0; i < D_IN; i++) s = fmaf(beta1[i], g_W1T[(size_t)i * D_EMB + t], s);
        g_b1eff[t] = s;
    }
    if (t < K_CB) g_hist[t] = 0u;
    if (t == 0) g_nneedy = 0;
}

// ---------------- K1: precompute A (bf16 hi/lo split) and Q --------------------
#define K1_ROWS 8
#define EPAD 12
__global__ __launch_bounds__(256) void k1_precompute(
    const float* __restrict__ emb, const float* __restrict__ W1,
    const float* __restrict__ g1v, const float* __restrict__ g2v,
    const float* __restrict__ beta2, const float* __restrict__ b2) {
    __shared__ float sE[D_EMB * EPAD];
    __shared__ float sG2[D_EMB];
    __shared__ float sB2[D_EMB];
    const int t = threadIdx.x;
    const int k0 = blockIdx.x * K1_ROWS;
    const float bn_s = rsqrtf(1.0f + 1e-5f);

    {
        int r = t & 7, ov = t >> 3;
        for (int pass = 0; pass < 4; pass++) {
            int o4 = ov + pass * 32;
            float4 v = *(const float4*)&emb[(size_t)(k0 + r) * D_EMB + o4 * 4];
            sE[(o4 * 4 + 0) * EPAD + r] = v.x;
            sE[(o4 * 4 + 1) * EPAD + r] = v.y;
            sE[(o4 * 4 + 2) * EPAD + r] = v.z;
            sE[(o4 * 4 + 3) * EPAD + r] = v.w;
        }
    }
    for (int i = t; i < D_EMB; i += 256) {
        sG2[i] = g2v[i] * bn_s;
        sB2[i] = beta2[i];
    }
    __syncthreads();

    const int j = t;
    float accA[K1_ROWS], accQ[K1_ROWS];
    float qc = 0.f;
#pragma unroll
    for (int r = 0; r < K1_ROWS; r++) { accA[r] = 0.f; accQ[r] = 0.f; }

#pragma unroll 4
    for (int o = 0; o < D_EMB; o++) {
        float w1 = W1[(size_t)o * D_IN + j];
        float w2 = g_W2T[(size_t)o * D_IN + j];
        float gw = sG2[o] * w2;
        qc = fmaf(sB2[o], w2, qc);
        const float* e = &sE[o * EPAD];
        float4 e0 = *(const float4*)(e + 0);
        float4 e1 = *(const float4*)(e + 4);
        float ev[8] = {e0.x, e0.y, e0.z, e0.w, e1.x, e1.y, e1.z, e1.w};
#pragma unroll
        for (int r = 0; r < K1_ROWS; r++) {
            accA[r] = fmaf(ev[r], w1, accA[r]);
            accQ[r] = fmaf(ev[r], gw, accQ[r]);
        }
    }
    float g1j = g1v[j] * bn_s;
    float b2j = b2[j];
#pragma unroll
    for (int r = 0; r < K1_ROWS; r++) {
        float a = g1j * accA[r];
        __nv_bfloat16 hi = __float2bfloat16(a);
        __nv_bfloat16 lo = __float2bfloat16(a - __bfloat162float(hi));
        g_Ahi[(size_t)(k0 + r) * D_IN + j] = hi;
        g_Alo[(size_t)(k0 + r) * D_IN + j] = lo;
        g_Q[(size_t)(k0 + r) * D_IN + j] = accQ[r] + qc + b2j;
    }
}

// ---------------- K1b: c[k] and se[k] ------------------------------------------
__global__ __launch_bounds__(256) void k1b_c(const float* __restrict__ emb) {
    int w = blockIdx.x * 8 + (threadIdx.x >> 5);
    int lane = threadIdx.x & 31;
    if (w >= K_CB) return;
    float s = 0.f, se = 0.f;
    for (int o = lane; o < D_EMB; o += 32) {
        float ev = emb[(size_t)w * D_EMB + o];
        s = fmaf(ev, g_b1eff[o] - 0.5f * ev, s);
        se = __fadd_rn(se, __fmul_rn(ev, ev));
    }
#pragma unroll
    for (int d = 16; d >= 1; d >>= 1) {
        s += __shfl_xor_sync(0xffffffffu, s, d);
        se = __fadd_rn(se, __shfl_xor_sync(0xffffffffu, se, d));
    }
    if (lane == 0) { g_c[w] = s; g_se[w] = se; }
}

// ---------------- K2: raw-PTX bf16 2-pass GEMM + in-register argmax ------------
// score = Fhi . (Ahi + Alo) + c  (Flo term dropped; MARGIN covers it)
__global__ __launch_bounds__(256, 1) void k2_mma(const float* __restrict__ inputs) {
    extern __shared__ __align__(16) char smem[];
    __nv_bfloat16* sFhi = (__nv_bfloat16*)smem;
    float* sC = (float*)(smem + OFF_C);
    float* sMv = (float*)(smem + OFF_MV);   // [2][128][3]
    int*   sMi = (int*)(smem + OFF_MI);
    const uint32_t sFu = smem_u32(smem);
    const uint32_t sA0u = sFu + OFF_A0;
    const uint32_t sA1u = sFu + OFF_A1;
    const int tid = threadIdx.x;
    const int wid = tid >> 5;
    const int lane = tid & 31;
    const int t0 = blockIdx.x * MT;
    const int tok0 = (wid & 3) * 32;
    const int half = wid >> 2;
    const int cb0l = half * 64;

    auto copy_tile = [&](int ct) {
        const char* srcH = (const char*)(g_Ahi + (size_t)ct * 128 * D_IN);
        const char* srcL = (const char*)(g_Alo + (size_t)ct * 128 * D_IN);
#pragma unroll
        for (int z = 0; z < 16; z++) {
            int idx = tid + z * 256;         // 0..4095
            int r = idx >> 5, u = idx & 31;
            uint32_t d0 = sA0u + (uint32_t)(r * (FLD * 2) + u * 16);
            uint32_t d1 = sA1u + (uint32_t)(r * (FLD * 2) + u * 16);
            const char* s0 = srcH + r * 512 + u * 16;
            const char* s1 = srcL + r * 512 + u * 16;
            asm volatile("cp.async.cg.shared.global [%0], [%1], 16;" :: "r"(d0), "l"(s0));
            asm volatile("cp.async.cg.shared.global [%0], [%1], 16;" :: "r"(d1), "l"(s1));
        }
    };

    for (int i = tid; i < K_CB; i += 256) sC[i] = g_c[i];
    copy_tile(0); CP_COMMIT();

    // stage tokens (bf16 hi only)
    for (int idx = tid; idx < MT * 64; idx += 256) {
        int tok = idx >> 6, q = idx & 63;
        float4 v = *(const float4*)&inputs[(size_t)(t0 + tok) * D_IN + q * 4];
        __nv_bfloat16 h0 = __float2bfloat16(v.x), h1 = __float2bfloat16(v.y);
        __nv_bfloat16 h2 = __float2bfloat16(v.z), h3 = __float2bfloat16(v.w);
        uint2 pk;
        pk.x = (uint32_t)__bfloat16_as_ushort(h0) | ((uint32_t)__bfloat16_as_ushort(h1) << 16);
        pk.y = (uint32_t)__bfloat16_as_ushort(h2) | ((uint32_t)__bfloat16_as_ushort(h3) << 16);
        *(uint2*)(sFhi + tok * FLD + q * 4) = pk;
    }

    // per-lane ldmatrix addresses
    const int g = lane >> 3, r = lane & 7;
    // A x4: m0:(t,k0) m1:(t+8,k0) m2:(t,k0+8) m3:(t+8,k0+8)
    const uint32_t aAddr = sFu + (uint32_t)(((tok0 + (g & 1) * 8 + r) * FLD + (g >> 1) * 8) * 2);
    // B x4 per pair p: m0:(n,k0) m1:(n,k0+8) m2:(n+8,k0) m3:(n+8,k0+8)
    const uint32_t bOff = (uint32_t)(((cb0l + (g >> 1) * 8 + r) * FLD + (g & 1) * 8) * 2);

    float tv0[4], tv1[4], tv2[4];
    int ti0[4], ti1[4], ti2[4];
#pragma unroll
    for (int s = 0; s < 4; s++) {
        tv0[s] = tv1[s] = tv2[s] = -INFINITY;
        ti0[s] = ti1[s] = ti2[s] = 0;
    }

    for (int ct = 0; ct < 16; ct++) {
        CP_WAIT0();
        __syncthreads();                 // tiles ready, all warps past prev reads
        float d[2][8][4];
#pragma unroll
        for (int mi = 0; mi < 2; mi++)
#pragma unroll
            for (int nt = 0; nt < 8; nt++)
#pragma unroll
                for (int e = 0; e < 4; e++) d[mi][nt][e] = 0.f;

#pragma unroll
        for (int ks = 0; ks < 16; ks++) {
            const uint32_t kb = (uint32_t)(ks * 32);   // 16 bf16 = 32 bytes
            uint32_t a[2][4], bh[4][4], bl[4][4];
            ldsm_x4(a[0], aAddr + kb);
            ldsm_x4(a[1], aAddr + 16 * FLD * 2 + kb);
#pragma unroll
            for (int p = 0; p < 4; p++) {
                ldsm_x4(bh[p], sA0u + bOff + (uint32_t)(p * 16 * FLD * 2) + kb);
                ldsm_x4(bl[p], sA1u + bOff + (uint32_t)(p * 16 * FLD * 2) + kb);
            }
#pragma unroll
            for (int mi = 0; mi < 2; mi++)
#pragma unroll
                for (int p = 0; p < 4; p++) {
                    mma16816(d[mi][2 * p + 0], a[mi], &bh[p][0]);
                    mma16816(d[mi][2 * p + 0], a[mi], &bl[p][0]);
                    mma16816(d[mi][2 * p + 1], a[mi], &bh[p][2]);
                    mma16816(d[mi][2 * p + 1], a[mi], &bl[p][2]);
                }
        }
        __syncthreads();                 // everyone done reading sA0/sA1
        if (ct < 15) { copy_tile(ct + 1); CP_COMMIT(); }

        // in-register top-3 update (ascending cb per thread)
        const int cbase = ct * 128 + cb0l + (lane & 3) * 2;
#pragma unroll
        for (int mi = 0; mi < 2; mi++)
#pragma unroll
            for (int h = 0; h < 2; h++) {
                const int s = mi * 2 + h;
                float v0r = tv0[s], v1r = tv1[s], v2r = tv2[s];
                int i0r = ti0[s], i1r = ti1[s], i2r = ti2[s];
#pragma unroll
                for (int nt = 0; nt < 8; nt++) {
#pragma unroll
                    for (int e = 0; e < 2; e++) {
                        int cb = cbase + nt * 8 + e;
                        float sv = d[mi][nt][h * 2 + e] + sC[cb];
                        if (sv > v2r) {
                            if (sv > v1r) {
                                if (sv > v0r) { v2r = v1r; i2r = i1r; v1r = v0r; i1r = i0r; v0r = sv; i0r = cb; }
                                else          { v2r = v1r; i2r = i1r; v1r = sv; i1r = cb; }
                            } else            { v2r = sv; i2r = cb; }
                        }
                    }
                }
                tv0[s] = v0r; tv1[s] = v1r; tv2[s] = v2r;
                ti0[s] = i0r; ti1[s] = i1r; ti2[s] = i2r;
            }
    }

    // quad butterfly merge (lanes differing in lane&3 hold disjoint cb columns)
#pragma unroll
    for (int m = 1; m <= 2; m++) {
#pragma unroll
        for (int s = 0; s < 4; s++) {
            float pv[3];
            int pi[3];
            pv[0] = __shfl_xor_sync(0xffffffffu, tv0[s], m); pi[0] = __shfl_xor_sync(0xffffffffu, ti0[s], m);
            pv[1] = __shfl_xor_sync(0xffffffffu, tv1[s], m); pi[1] = __shfl_xor_sync(0xffffffffu, ti1[s], m);
            pv[2] = __shfl_xor_sync(0xffffffffu, tv2[s], m); pi[2] = __shfl_xor_sync(0xffffffffu, ti2[s], m);
#pragma unroll
            for (int e = 0; e < 3; e++) {
                float sv = pv[e]; int cb = pi[e];
                bool b0 = sv > tv0[s] || (sv == tv0[s] && cb < ti0[s]);
                bool b1 = sv > tv1[s] || (sv == tv1[s] && cb < ti1[s]);
                bool b2 = sv > tv2[s] || (sv == tv2[s] && cb < ti2[s]);
                if (b0) { tv2[s] = tv1[s]; ti2[s] = ti1[s]; tv1[s] = tv0[s]; ti1[s] = ti0[s]; tv0[s] = sv; ti0[s] = cb; }
                else if (b1) { tv2[s] = tv1[s]; ti2[s] = ti1[s]; tv1[s] = sv; ti1[s] = cb; }
                else if (b2) { tv2[s] = sv; ti2[s] = cb; }
            }
        }
    }
    if ((lane & 3) == 0) {
#pragma unroll
        for (int s = 0; s < 4; s++) {
            int tokl = tok0 + (s >> 1) * 16 + (lane >> 2) + (s & 1) * 8;
            float* mv = sMv + (half * 128 + tokl) * 3;
            int* mi = sMi + (half * 128 + tokl) * 3;
            mv[0] = tv0[s]; mv[1] = tv1[s]; mv[2] = tv2[s];
            mi[0] = ti0[s]; mi[1] = ti1[s]; mi[2] = ti2[s];
        }
    }
    __syncthreads();

    if (tid < 128) {
        const float* mv0 = sMv + tid * 3;
        const int* mi0 = sMi + tid * 3;
        const float* mv1 = sMv + (128 + tid) * 3;
        const int* mi1 = sMi + (128 + tid) * 3;
        float v0 = mv0[0], v1 = mv0[1], v2 = mv0[2];
        int i0 = mi0[0], i1 = mi0[1], i2 = mi0[2];
#pragma unroll
        for (int e = 0; e < 3; e++) {
            float sv = mv1[e]; int cb = mi1[e];
            bool b0 = sv > v0 || (sv == v0 && cb < i0);
            bool b1 = sv > v1 || (sv == v1 && cb < i1);
            bool b2 = sv > v2 || (sv == v2 && cb < i2);
            if (b0) { v2 = v1; i2 = i1; v1 = v0; i1 = i0; v0 = sv; i0 = cb; }
            else if (b1) { v2 = v1; i2 = i1; v1 = sv; i1 = cb; }
            else if (b2) { v2 = sv; i2 = cb; }
        }
        int tok = t0 + tid;
        float thr = v0 - MARGIN;
        if (v2 >= thr) {
            g_ccount[tok] = 17;
            int p = atomicAdd(&g_nneedy, 1);
            g_needy[p] = tok;
        } else if (v1 >= thr) {
            g_ccount[tok] = 2;
            g_cand[tok][0] = (unsigned short)i0;
            g_cand[tok][1] = (unsigned short)i1;
            int p = atomicAdd(&g_nneedy, 1);
            g_needy[p] = tok;
        } else {
            g_ccount[tok] = 1;
            g_idx[tok] = i0;
            atomicAdd(&g_hist[i0], 1u);
        }
    }
}

// ---------------- K_exact: jax-emulated fp32 distances, 4-token batches --------
__global__ __launch_bounds__(256) void k_exact(
    const float* __restrict__ inputs, const float* __restrict__ g1v,
    const float* __restrict__ beta1, const float* __restrict__ b1,
    const float* __restrict__ emb, float S) {
    __shared__ float sXin[4][D_IN];
    __shared__ float sX[4][D_EMB];
    __shared__ float sRed[256];
    __shared__ int sRedI[256];
    __shared__ float sSx[4];
    __shared__ int sTok[4];
    const int tid = threadIdx.x;
    const int n = g_nneedy;
    for (int base = blockIdx.x * 4; base < n; base += gridDim.x * 4) {
        int nb = n - base; if (nb > 4) nb = 4;
        if (tid < 4) sTok[tid] = g_needy[base + (tid < nb ? tid : 0)];
        __syncthreads();
        {
            float sc = __fmul_rn(g1v[tid], S);
            float bt = beta1[tid];
#pragma unroll
            for (int j = 0; j < 4; j++) {
                float f = inputs[(size_t)sTok[j] * D_IN + tid];
                sXin[j][tid] = __fadd_rn(__fmul_rn(f, sc), bt);
            }
        }
        __syncthreads();
        if (tid < 128) {
            int ob = tid * 4;
            float a[4][4];
#pragma unroll
            for (int j = 0; j < 4; j++)
#pragma unroll
                for (int c = 0; c < 4; c++) a[j][c] = 0.f;
#pragma unroll 4
            for (int i = 0; i < D_IN; i++) {
                float4 w = *(const float4*)(g_W1T + (size_t)i * D_EMB + ob);
#pragma unroll
                for (int j = 0; j < 4; j++) {
                    float xi = sXin[j][i];
                    a[j][0] = fmaf(xi, w.x, a[j][0]);
                    a[j][1] = fmaf(xi, w.y, a[j][1]);
                    a[j][2] = fmaf(xi, w.z, a[j][2]);
                    a[j][3] = fmaf(xi, w.w, a[j][3]);
                }
            }
#pragma unroll
            for (int j = 0; j < 4; j++) {
                sX[j][ob + 0] = __fadd_rn(a[j][0], b1[ob + 0]);
                sX[j][ob + 1] = __fadd_rn(a[j][1], b1[ob + 1]);
                sX[j][ob + 2] = __fadd_rn(a[j][2], b1[ob + 2]);
                sX[j][ob + 3] = __fadd_rn(a[j][3], b1[ob + 3]);
            }
        }
        __syncthreads();
        {
            float p[4];
#pragma unroll
            for (int j = 0; j < 4; j++)
                p[j] = __fadd_rn(__fmul_rn(sX[j][tid], sX[j][tid]),
                                 __fmul_rn(sX[j][tid + 256], sX[j][tid + 256]));
#pragma unroll
            for (int d = 16; d >= 1; d >>= 1)
#pragma unroll
                for (int j = 0; j < 4; j++)
                    p[j] = __fadd_rn(p[j], __shfl_xor_sync(0xffffffffu, p[j], d));
            if ((tid & 31) == 0)
#pragma unroll
                for (int j = 0; j < 4; j++) sRed[j * 8 + (tid >> 5)] = p[j];
            __syncthreads();
            if (tid < 4) {
                float s = 0.f;
#pragma unroll
                for (int w = 0; w < 8; w++) s = __fadd_rn(s, sRed[tid * 8 + w]);
                sSx[tid] = s;
            }
            __syncthreads();
        }
        for (int j = 0; j < nb; j++) {
            int t = sTok[j];
            float sx = sSx[j];
            int cnt = g_ccount[t];
            int C = (cnt <= 16) ? cnt : K_CB;
            float bd = INFINITY;
            int bk = 0x7fffffff;
            for (int ci = tid; ci < C; ci += 256) {
                int k = (cnt <= 16) ? (int)g_cand[t][ci] : ci;
                const float4* e4 = (const float4*)(emb + (size_t)k * D_EMB);
                float m = 0.f;
#pragma unroll 4
                for (int o4 = 0; o4 < D_EMB / 4; o4++) {
                    float4 e = e4[o4];
                    m = fmaf(sX[j][o4 * 4 + 0], e.x, m);
                    m = fmaf(sX[j][o4 * 4 + 1], e.y, m);
                    m = fmaf(sX[j][o4 * 4 + 2], e.z, m);
                    m = fmaf(sX[j][o4 * 4 + 3], e.w, m);
                }
                float d = __fsub_rn(__fadd_rn(sx, g_se[k]), __fmul_rn(2.0f, m));
                if (d < bd || (d == bd && k < bk)) { bd = d; bk = k; }
            }
            sRed[tid] = bd; sRedI[tid] = bk;
            __syncthreads();
            for (int d = 128; d >= 1; d >>= 1) {
                if (tid < d) {
                    float od = sRed[tid + d]; int ok = sRedI[tid + d];
                    if (od < sRed[tid] || (od == sRed[tid] && ok < sRedI[tid])) {
                        sRed[tid] = od; sRedI[tid] = ok;
                    }
                }
                __syncthreads();
            }
            if (tid == 0) { g_idx[t] = sRedI[0]; atomicAdd(&g_hist[sRedI[0]], 1u); }
            __syncthreads();
        }
    }
}

// ---------------- K3: gather + straight-through + SSE partials -----------------
__global__ __launch_bounds__(256) void k3_gather(const float* __restrict__ inputs,
                                                 float* __restrict__ outq) {
    const int t = threadIdx.x;
    float s = 0.f;
#pragma unroll
    for (int r = 0; r < 8; r++) {
        int gid = blockIdx.x * 2048 + r * 256 + t;
        int tok = gid >> 8;
        int j = gid & 255;
        int idx = g_idx[tok];
        float q = g_Q[(size_t)idx * D_IN + j];
        float x = inputs[gid];
        float d = __fsub_rn(q, x);
        outq[gid] = __fadd_rn(x, d);
        s = fmaf(d, d, s);
    }
#pragma unroll
    for (int d = 16; d >= 1; d >>= 1) s += __shfl_xor_sync(0xffffffffu, s, d);
    __shared__ float wsum[8];
    if ((t & 31) == 0) wsum[t >> 5] = s;
    __syncthreads();
    if (t == 0) {
        float tot = 0.f;
#pragma unroll
        for (int w = 0; w < 8; w++) tot += wsum[w];
        g_partial[blockIdx.x] = (double)tot;
    }
}

// ---------------- K4: loss + usage ---------------------------------------------
__global__ void k4_final(float* __restrict__ out, int T) {
    int t = blockIdx.x * 256 + threadIdx.x;
    if (t < K_CB) out[1 + (size_t)T * D_IN + t] = (float)g_hist[t] * (1.0f / (float)T);
    if (blockIdx.x == 0) {
        double s = 0.0;
        for (int i = threadIdx.x; i < 8192; i += 256) s += g_partial[i];
        __shared__ double sh[256];
        sh[threadIdx.x] = s;
        __syncthreads();
        for (int d = 128; d >= 1; d >>= 1) {
            if (threadIdx.x < d) sh[threadIdx.x] += sh[threadIdx.x + d];
            __syncthreads();
        }
        if (threadIdx.x == 0)
            out[0] = (float)(1.25 * sh[0] / ((double)T * (double)D_IN));
    }
}

// ---------------- launch --------------------------------------------------------
extern "C" void kernel_launch(void* const* d_in, const int* in_sizes, int n_in,
                              void* d_out, int out_size) {
    const float* inputs    = (const float*)d_in[0];
    const float* bn1_gamma = (const float*)d_in[1];
    const float* bn1_beta  = (const float*)d_in[2];
    const float* W1        = (const float*)d_in[3];
    const float* b1        = (const float*)d_in[4];
    const float* emb       = (const float*)d_in[5];
    const float* bn2_gamma = (const float*)d_in[6];
    const float* bn2_beta  = (const float*)d_in[7];
    const float* W2        = (const float*)d_in[8];
    const float* b2        = (const float*)d_in[9];
    float* out = (float*)d_out;
    const int T = in_sizes[0] / D_IN;   // 65536

    float af = (float)(1.0 + 1e-5);
    float S = 1.0f / sqrtf(af);

    float* w1t; cudaGetSymbolAddress((void**)&w1t, g_W1T);
    float* w2t; cudaGetSymbolAddress((void**)&w2t, g_W2T);

    {
        dim3 blk(32, 8);
        kT_transpose<<<dim3(D_IN / 32, D_EMB / 32), blk>>>(W1, w1t, D_EMB, D_IN);
        kT_transpose<<<dim3(D_EMB / 32, D_IN / 32), blk>>>(W2, w2t, D_IN, D_EMB);
    }
    k0_init<<<8, 256>>>(b1, bn1_beta);
    k1_precompute<<<K_CB / K1_ROWS, 256>>>(emb, W1, bn1_gamma, bn2_gamma, bn2_beta, b2);
    k1b_c<<<K_CB / 8, 256>>>(emb);
    cudaFuncSetAttribute(k2_mma, cudaFuncAttributeMaxDynamicSharedMemorySize, K2_SMEM);
    k2_mma<<<T / MT, 256, K2_SMEM>>>(inputs);
    k_exact<<<NB_EXACT, 256>>>(inputs, bn1_gamma, bn1_beta, b1, emb, S);
    k3_gather<<<8192, 256>>>(inputs, out + 1);
    k4_final<<<8, 256>>>(out, T);
}

// round 14
// speedup vs baseline: 1.0567x; 1.0567x over previous
#include <cuda_runtime.h>
#include <cuda_bf16.h>
#include <mma.h>
#include <math.h>
#include <stdint.h>

using namespace nvcuda;

#define D_IN   256
#define D_EMB  512
#define K_CB   2048
#define T_MAX  65536
#define MARGIN 3.0e-4f
#define NB_EXACT 2048

#define MT   128                 // tokens per CTA
#define FLD  264                 // bf16 pitch for token/A tiles
#define OLD  132                 // float pitch for output scan buffer
#define SZ_F (MT * FLD * 2)      // 67584 bytes
#define OFF_A   (SZ_F)           // A tile buffer (sFlo eliminated)
#define OFF_C   (2 * SZ_F)
#define K2W_SMEM (2 * SZ_F + K_CB * 4)   // 143360

// ---------------- scratch (device globals; no allocations allowed) -----------
__device__ __align__(16) float g_Q[K_CB * D_IN];
__device__ __align__(16) float g_W1T[D_IN * D_EMB];
__device__ __align__(16) float g_W2T[D_EMB * D_IN];
__device__ __align__(16) __nv_bfloat16 g_Ahi[K_CB * D_IN];  // [cb][i] row-major
__device__ __align__(16) __nv_bfloat16 g_Alo[K_CB * D_IN];
__device__ float g_c[K_CB];
__device__ float g_se[K_CB];
__device__ float g_b1eff[D_EMB];
__device__ int g_idx[T_MAX];
__device__ unsigned int g_hist[K_CB];
__device__ double g_partial[8192];
__device__ int g_ccount[T_MAX];
__device__ unsigned short g_cand[T_MAX][16];
__device__ int g_needy[T_MAX];
__device__ int g_nneedy;

static __device__ __forceinline__ uint32_t smem_u32(const void* p) {
    uint32_t a;
    asm("{ .reg .u64 t; cvta.to.shared.u64 t, %1; cvt.u32.u64 %0, t; }" : "=r"(a) : "l"(p));
    return a;
}
#define CP_COMMIT() asm volatile("cp.async.commit_group;" ::: "memory")
#define CP_WAIT(n)  asm volatile("cp.async.wait_group %0;" :: "n"(n) : "memory")

// ---------------- KT: tiled transpose ----------------------------------------
__global__ void kT_transpose(const float* __restrict__ src, float* __restrict__ dst,
                             int R, int C) {
    __shared__ float tile[32][33];
    int bx = blockIdx.x * 32, by = blockIdx.y * 32;
    int x = bx + threadIdx.x;
    int y = by + threadIdx.y;
#pragma unroll
    for (int j = 0; j < 32; j += 8)
        if (y + j < R && x < C) tile[threadIdx.y + j][threadIdx.x] = src[(size_t)(y + j) * C + x];
    __syncthreads();
    x = by + threadIdx.x;
    y = bx + threadIdx.y;
#pragma unroll
    for (int j = 0; j < 32; j += 8)
        if (y + j < C && x < R) dst[(size_t)(y + j) * R + x] = tile[threadIdx.x][threadIdx.y + j];
}

// ---------------- K0 -----------------------------------------------------------
__global__ void k0_init(const float* __restrict__ b1, const float* __restrict__ beta1) {
    int t = blockIdx.x * blockDim.x + threadIdx.x;
    if (t < D_EMB) {
        float s = b1[t];
        for (int i = 0; i < D_IN; i++) s = fmaf(beta1[i], g_W1T[(size_t)i * D_EMB + t], s);
        g_b1eff[t] = s;
    }
    if (t < K_CB) g_hist[t] = 0u;
    if (t == 0) g_nneedy = 0;
}

// ---------------- K1: precompute A (bf16 hi/lo split) and Q --------------------
#define K1_ROWS 8
#define EPAD 12
__global__ __launch_bounds__(256) void k1_precompute(
    const float* __restrict__ emb, const float* __restrict__ W1,
    const float* __restrict__ g1v, const float* __restrict__ g2v,
    const float* __restrict__ beta2, const float* __restrict__ b2) {
    __shared__ float sE[D_EMB * EPAD];
    __shared__ float sG2[D_EMB];
    __shared__ float sB2[D_EMB];
    const int t = threadIdx.x;
    const int k0 = blockIdx.x * K1_ROWS;
    const float bn_s = rsqrtf(1.0f + 1e-5f);

    {
        int r = t & 7, ov = t >> 3;
        for (int pass = 0; pass < 4; pass++) {
            int o4 = ov + pass * 32;
            float4 v = *(const float4*)&emb[(size_t)(k0 + r) * D_EMB + o4 * 4];
            sE[(o4 * 4 + 0) * EPAD + r] = v.x;
            sE[(o4 * 4 + 1) * EPAD + r] = v.y;
            sE[(o4 * 4 + 2) * EPAD + r] = v.z;
            sE[(o4 * 4 + 3) * EPAD + r] = v.w;
        }
    }
    for (int i = t; i < D_EMB; i += 256) {
        sG2[i] = g2v[i] * bn_s;
        sB2[i] = beta2[i];
    }
    __syncthreads();

    const int j = t;
    float accA[K1_ROWS], accQ[K1_ROWS];
    float qc = 0.f;
#pragma unroll
    for (int r = 0; r < K1_ROWS; r++) { accA[r] = 0.f; accQ[r] = 0.f; }

#pragma unroll 4
    for (int o = 0; o < D_EMB; o++) {
        float w1 = W1[(size_t)o * D_IN + j];
        float w2 = g_W2T[(size_t)o * D_IN + j];
        float gw = sG2[o] * w2;
        qc = fmaf(sB2[o], w2, qc);
        const float* e = &sE[o * EPAD];
        float4 e0 = *(const float4*)(e + 0);
        float4 e1 = *(const float4*)(e + 4);
        float ev[8] = {e0.x, e0.y, e0.z, e0.w, e1.x, e1.y, e1.z, e1.w};
#pragma unroll
        for (int r = 0; r < K1_ROWS; r++) {
            accA[r] = fmaf(ev[r], w1, accA[r]);
            accQ[r] = fmaf(ev[r], gw, accQ[r]);
        }
    }
    float g1j = g1v[j] * bn_s;
    float b2j = b2[j];
#pragma unroll
    for (int r = 0; r < K1_ROWS; r++) {
        float a = g1j * accA[r];
        __nv_bfloat16 hi = __float2bfloat16(a);
        __nv_bfloat16 lo = __float2bfloat16(a - __bfloat162float(hi));
        g_Ahi[(size_t)(k0 + r) * D_IN + j] = hi;
        g_Alo[(size_t)(k0 + r) * D_IN + j] = lo;
        g_Q[(size_t)(k0 + r) * D_IN + j] = accQ[r] + qc + b2j;
    }
}

// ---------------- K1b: c[k] and se[k] ------------------------------------------
__global__ __launch_bounds__(256) void k1b_c(const float* __restrict__ emb) {
    int w = blockIdx.x * 8 + (threadIdx.x >> 5);
    int lane = threadIdx.x & 31;
    if (w >= K_CB) return;
    float s = 0.f, se = 0.f;
    for (int o = lane; o < D_EMB; o += 32) {
        float ev = emb[(size_t)w * D_EMB + o];
        s = fmaf(ev, g_b1eff[o] - 0.5f * ev, s);
        se = __fadd_rn(se, __fmul_rn(ev, ev));
    }
#pragma unroll
    for (int d = 16; d >= 1; d >>= 1) {
        s += __shfl_xor_sync(0xffffffffu, s, d);
        se = __fadd_rn(se, __shfl_xor_sync(0xffffffffu, se, d));
    }
    if (lane == 0) { g_c[w] = s; g_se[w] = se; }
}

// ---------------- K2: wmma bf16 2-pass GEMM, cp.async chunk pipeline -----------
// score = Fhi.Ahi + Fhi.Alo + c   (Flo term dropped; MARGIN widened to cover)
__global__ __launch_bounds__(256, 1) void k2_wmma(const float* __restrict__ inputs) {
    extern __shared__ __align__(16) char smem[];
    __nv_bfloat16* sFhi = (__nv_bfloat16*)smem;
    __nv_bfloat16* sA   = (__nv_bfloat16*)(smem + OFF_A);
    float* sOut = (float*)(smem + OFF_A);          // reuses A buffer
    float* sC   = (float*)(smem + OFF_C);
    const int tid = threadIdx.x;
    const int wid = tid >> 5;
    const int t0 = blockIdx.x * MT;
    const int tok0 = (wid & 3) * 32;
    const int cb0l = (wid >> 2) * 64;
    const uint32_t sAu = smem_u32(sA);

    for (int i = tid; i < K_CB; i += 256) sC[i] = g_c[i];

    // stage tokens (bf16 hi only, row-major [tok][FLD])
    for (int idx = tid; idx < MT * 64; idx += 256) {
        int tok = idx >> 6, q = idx & 63;
        float4 v = *(const float4*)&inputs[(size_t)(t0 + tok) * D_IN + q * 4];
        __nv_bfloat16 h0 = __float2bfloat16(v.x), h1 = __float2bfloat16(v.y);
        __nv_bfloat16 h2 = __float2bfloat16(v.z), h3 = __float2bfloat16(v.w);
        uint2 pk;
        pk.x = (uint32_t)__bfloat16_as_ushort(h0) | ((uint32_t)__bfloat16_as_ushort(h1) << 16);
        pk.y = (uint32_t)__bfloat16_as_ushort(h2) | ((uint32_t)__bfloat16_as_ushort(h3) << 16);
        *(uint2*)(sFhi + tok * FLD + q * 4) = pk;
    }

    float v0 = -INFINITY, v1 = -INFINITY, v2 = -INFINITY;
    int i0 = 0, i1 = 0, i2 = 0;

    wmma::fragment<wmma::accumulator, 16, 16, 16, float> acc[2][4];

    // chunk = K-half (128 k = bytes [chunk*256, chunk*256+256) of each 528B row)
    auto copy_chunk = [&](const __nv_bfloat16* gbase, int chunk) {
        const char* src = (const char*)gbase;
#pragma unroll
        for (int z = 0; z < 8; z++) {
            int idx = tid + z * 256;            // 0..2047
            int r = idx >> 4, u = idx & 15;
            uint32_t d = sAu + (uint32_t)(r * (FLD * 2) + chunk * 256 + u * 16);
            const char* s = src + r * 512 + chunk * 256 + u * 16;
            asm volatile("cp.async.cg.shared.global [%0], [%1], 16;" :: "r"(d), "l"(s));
        }
    };
    auto mma_pass = [&](int chunk) {
#pragma unroll
        for (int ks = 0; ks < 8; ks++) {
            int k0 = (chunk * 8 + ks) * 16;
            wmma::fragment<wmma::matrix_a, 16, 16, 16, __nv_bfloat16, wmma::row_major> ah[2];
            wmma::fragment<wmma::matrix_b, 16, 16, 16, __nv_bfloat16, wmma::col_major> b[4];
#pragma unroll
            for (int mi = 0; mi < 2; mi++)
                wmma::load_matrix_sync(ah[mi], sFhi + (tok0 + mi * 16) * FLD + k0, FLD);
#pragma unroll
            for (int ni = 0; ni < 4; ni++)
                wmma::load_matrix_sync(b[ni], sA + (cb0l + ni * 16) * FLD + k0, FLD);
#pragma unroll
            for (int ni = 0; ni < 4; ni++)
#pragma unroll
                for (int mi = 0; mi < 2; mi++)
                    wmma::mma_sync(acc[mi][ni], ah[mi], b[ni], acc[mi][ni]);
        }
    };

    for (int ct = 0; ct < 16; ct++) {
        __syncthreads();                 // prev scan done (or token staging), sA free
        const __nv_bfloat16* baseHi = g_Ahi + (size_t)ct * 128 * D_IN;
        const __nv_bfloat16* baseLo = g_Alo + (size_t)ct * 128 * D_IN;
        copy_chunk(baseHi, 0); CP_COMMIT();      // g1: Hi chunk0
        copy_chunk(baseHi, 1); CP_COMMIT();      // g2: Hi chunk1
#pragma unroll
        for (int mi = 0; mi < 2; mi++)
#pragma unroll
            for (int ni = 0; ni < 4; ni++) wmma::fill_fragment(acc[mi][ni], 0.0f);
        CP_WAIT(1); __syncthreads();             // Hi0 ready
        mma_pass(0);                             // Fhi.Ahi (k 0..127)
        __syncthreads();                          // chunk0 readers done
        copy_chunk(baseLo, 0); CP_COMMIT();      // g3: Lo chunk0 (overlaps next pass)
        CP_WAIT(1); __syncthreads();             // Hi1 ready
        mma_pass(1);                             // Fhi.Ahi (k 128..255)
        __syncthreads();                          // chunk1 readers done
        copy_chunk(baseLo, 1); CP_COMMIT();      // g4: Lo chunk1
        CP_WAIT(1); __syncthreads();             // Lo0 ready
        mma_pass(0);                             // Fhi.Alo (k 0..127)
        CP_WAIT(0); __syncthreads();             // Lo1 ready
        mma_pass(1);                             // Fhi.Alo (k 128..255)
        __syncthreads();                          // all mma done; sA -> sOut
#pragma unroll
        for (int mi = 0; mi < 2; mi++)
#pragma unroll
            for (int ni = 0; ni < 4; ni++)
                wmma::store_matrix_sync(sOut + (tok0 + mi * 16) * OLD + cb0l + ni * 16,
                                        acc[mi][ni], OLD, wmma::mem_row_major);
        __syncthreads();
        {   // scan: 2 threads per token, 64 cb each, ascending index
            int tok = tid >> 1, half = tid & 1;
            const float* row = sOut + tok * OLD + half * 64;
            const float* cc = sC + ct * 128 + half * 64;
            int cbb = ct * 128 + half * 64;
#pragma unroll 4
            for (int j = 0; j < 64; j++) {
                float s = row[j] + cc[j];
                if (s > v2) {
                    int cb = cbb + j;
                    if (s > v1) {
                        if (s > v0) { v2 = v1; i2 = i1; v1 = v0; i1 = i0; v0 = s; i0 = cb; }
                        else        { v2 = v1; i2 = i1; v1 = s; i1 = cb; }
                    } else          { v2 = s; i2 = cb; }
                }
            }
        }
    }

    // merge the two half-scans of each token (value desc, index asc)
    {
        float pv[3];
        int pi[3];
        pv[0] = __shfl_xor_sync(0xffffffffu, v0, 1); pi[0] = __shfl_xor_sync(0xffffffffu, i0, 1);
        pv[1] = __shfl_xor_sync(0xffffffffu, v1, 1); pi[1] = __shfl_xor_sync(0xffffffffu, i1, 1);
        pv[2] = __shfl_xor_sync(0xffffffffu, v2, 1); pi[2] = __shfl_xor_sync(0xffffffffu, i2, 1);
#pragma unroll
        for (int e = 0; e < 3; e++) {
            float s = pv[e]; int cb = pi[e];
            bool b0 = s > v0 || (s == v0 && cb < i0);
            bool b1 = s > v1 || (s == v1 && cb < i1);
            bool b2 = s > v2 || (s == v2 && cb < i2);
            if (b0) { v2 = v1; i2 = i1; v1 = v0; i1 = i0; v0 = s; i0 = cb; }
            else if (b1) { v2 = v1; i2 = i1; v1 = s; i1 = cb; }
            else if (b2) { v2 = s; i2 = cb; }
        }
    }
    if ((tid & 1) == 0) {
        int tok = t0 + (tid >> 1);
        float thr = v0 - MARGIN;
        if (v2 >= thr) {
            g_ccount[tok] = 17;
            int p = atomicAdd(&g_nneedy, 1);
            g_needy[p] = tok;
        } else if (v1 >= thr) {
            g_ccount[tok] = 2;
            g_cand[tok][0] = (unsigned short)i0;
            g_cand[tok][1] = (unsigned short)i1;
            int p = atomicAdd(&g_nneedy, 1);
            g_needy[p] = tok;
        } else {
            g_ccount[tok] = 1;
            g_idx[tok] = i0;
            atomicAdd(&g_hist[i0], 1u);
        }
    }
}

// ---------------- K_exact: jax-emulated fp32 distances, 4-token batches --------
__global__ __launch_bounds__(256) void k_exact(
    const float* __restrict__ inputs, const float* __restrict__ g1v,
    const float* __restrict__ beta1, const float* __restrict__ b1,
    const float* __restrict__ emb, float S) {
    __shared__ float sXin[4][D_IN];
    __shared__ float sX[4][D_EMB];
    __shared__ float sRed[256];
    __shared__ int sRedI[256];
    __shared__ float sSx[4];
    __shared__ int sTok[4];
    const int tid = threadIdx.x;
    const int n = g_nneedy;
    for (int base = blockIdx.x * 4; base < n; base += gridDim.x * 4) {
        int nb = n - base; if (nb > 4) nb = 4;
        if (tid < 4) sTok[tid] = g_needy[base + (tid < nb ? tid : 0)];
        __syncthreads();
        {
            float sc = __fmul_rn(g1v[tid], S);
            float bt = beta1[tid];
#pragma unroll
            for (int j = 0; j < 4; j++) {
                float f = inputs[(size_t)sTok[j] * D_IN + tid];
                sXin[j][tid] = __fadd_rn(__fmul_rn(f, sc), bt);
            }
        }
        __syncthreads();
        if (tid < 128) {
            int ob = tid * 4;
            float a[4][4];
#pragma unroll
            for (int j = 0; j < 4; j++)
#pragma unroll
                for (int c = 0; c < 4; c++) a[j][c] = 0.f;
#pragma unroll 4
            for (int i = 0; i < D_IN; i++) {
                float4 w = *(const float4*)(g_W1T + (size_t)i * D_EMB + ob);
#pragma unroll
                for (int j = 0; j < 4; j++) {
                    float xi = sXin[j][i];
                    a[j][0] = fmaf(xi, w.x, a[j][0]);
                    a[j][1] = fmaf(xi, w.y, a[j][1]);
                    a[j][2] = fmaf(xi, w.z, a[j][2]);
                    a[j][3] = fmaf(xi, w.w, a[j][3]);
                }
            }
#pragma unroll
            for (int j = 0; j < 4; j++) {
                sX[j][ob + 0] = __fadd_rn(a[j][0], b1[ob + 0]);
                sX[j][ob + 1] = __fadd_rn(a[j][1], b1[ob + 1]);
                sX[j][ob + 2] = __fadd_rn(a[j][2], b1[ob + 2]);
                sX[j][ob + 3] = __fadd_rn(a[j][3], b1[ob + 3]);
            }
        }
        __syncthreads();
        {
            float p[4];
#pragma unroll
            for (int j = 0; j < 4; j++)
                p[j] = __fadd_rn(__fmul_rn(sX[j][tid], sX[j][tid]),
                                 __fmul_rn(sX[j][tid + 256], sX[j][tid + 256]));
#pragma unroll
            for (int d = 16; d >= 1; d >>= 1)
#pragma unroll
                for (int j = 0; j < 4; j++)
                    p[j] = __fadd_rn(p[j], __shfl_xor_sync(0xffffffffu, p[j], d));
            if ((tid & 31) == 0)
#pragma unroll
                for (int j = 0; j < 4; j++) sRed[j * 8 + (tid >> 5)] = p[j];
            __syncthreads();
            if (tid < 4) {
                float s = 0.f;
#pragma unroll
                for (int w = 0; w < 8; w++) s = __fadd_rn(s, sRed[tid * 8 + w]);
                sSx[tid] = s;
            }
            __syncthreads();
        }
        for (int j = 0; j < nb; j++) {
            int t = sTok[j];
            float sx = sSx[j];
            int cnt = g_ccount[t];
            int C = (cnt <= 16) ? cnt : K_CB;
            float bd = INFINITY;
            int bk = 0x7fffffff;
            for (int ci = tid; ci < C; ci += 256) {
                int k = (cnt <= 16) ? (int)g_cand[t][ci] : ci;
                const float4* e4 = (const float4*)(emb + (size_t)k * D_EMB);
                float m = 0.f;
#pragma unroll 4
                for (int o4 = 0; o4 < D_EMB / 4; o4++) {
                    float4 e = e4[o4];
                    m = fmaf(sX[j][o4 * 4 + 0], e.x, m);
                    m = fmaf(sX[j][o4 * 4 + 1], e.y, m);
                    m = fmaf(sX[j][o4 * 4 + 2], e.z, m);
                    m = fmaf(sX[j][o4 * 4 + 3], e.w, m);
                }
                float d = __fsub_rn(__fadd_rn(sx, g_se[k]), __fmul_rn(2.0f, m));
                if (d < bd || (d == bd && k < bk)) { bd = d; bk = k; }
            }
            sRed[tid] = bd; sRedI[tid] = bk;
            __syncthreads();
            for (int d = 128; d >= 1; d >>= 1) {
                if (tid < d) {
                    float od = sRed[tid + d]; int ok = sRedI[tid + d];
                    if (od < sRed[tid] || (od == sRed[tid] && ok < sRedI[tid])) {
                        sRed[tid] = od; sRedI[tid] = ok;
                    }
                }
                __syncthreads();
            }
            if (tid == 0) { g_idx[t] = sRedI[0]; atomicAdd(&g_hist[sRedI[0]], 1u); }
            __syncthreads();
        }
    }
}

// ---------------- K3: gather + straight-through + SSE partials -----------------
__global__ __launch_bounds__(256) void k3_gather(const float* __restrict__ inputs,
                                                 float* __restrict__ outq) {
    const int t = threadIdx.x;
    float s = 0.f;
#pragma unroll
    for (int r = 0; r < 8; r++) {
        int gid = blockIdx.x * 2048 + r * 256 + t;
        int tok = gid >> 8;
        int j = gid & 255;
        int idx = g_idx[tok];
        float q = g_Q[(size_t)idx * D_IN + j];
        float x = inputs[gid];
        float d = __fsub_rn(q, x);
        outq[gid] = __fadd_rn(x, d);
        s = fmaf(d, d, s);
    }
#pragma unroll
    for (int d = 16; d >= 1; d >>= 1) s += __shfl_xor_sync(0xffffffffu, s, d);
    __shared__ float wsum[8];
    if ((t & 31) == 0) wsum[t >> 5] = s;
    __syncthreads();
    if (t == 0) {
        float tot = 0.f;
#pragma unroll
        for (int w = 0; w < 8; w++) tot += wsum[w];
        g_partial[blockIdx.x] = (double)tot;
    }
}

// ---------------- K4: loss + usage ---------------------------------------------
__global__ void k4_final(float* __restrict__ out, int T) {
    int t = blockIdx.x * 256 + threadIdx.x;
    if (t < K_CB) out[1 + (size_t)T * D_IN + t] = (float)g_hist[t] * (1.0f / (float)T);
    if (blockIdx.x == 0) {
        double s = 0.0;
        for (int i = threadIdx.x; i < 8192; i += 256) s += g_partial[i];
        __shared__ double sh[256];
        sh[threadIdx.x] = s;
        __syncthreads();
        for (int d = 128; d >= 1; d >>= 1) {
            if (threadIdx.x < d) sh[threadIdx.x] += sh[threadIdx.x + d];
            __syncthreads();
        }
        if (threadIdx.x == 0)
            out[0] = (float)(1.25 * sh[0] / ((double)T * (double)D_IN));
    }
}

// ---------------- launch --------------------------------------------------------
extern "C" void kernel_launch(void* const* d_in, const int* in_sizes, int n_in,
                              void* d_out, int out_size) {
    const float* inputs    = (const float*)d_in[0];
    const float* bn1_gamma = (const float*)d_in[1];
    const float* bn1_beta  = (const float*)d_in[2];
    const float* W1        = (const float*)d_in[3];
    const float* b1        = (const float*)d_in[4];
    const float* emb       = (const float*)d_in[5];
    const float* bn2_gamma = (const float*)d_in[6];
    const float* bn2_beta  = (const float*)d_in[7];
    const float* W2        = (const float*)d_in[8];
    const float* b2        = (const float*)d_in[9];
    float* out = (float*)d_out;
    const int T = in_sizes[0] / D_IN;   // 65536

    float af = (float)(1.0 + 1e-5);
    float S = 1.0f / sqrtf(af);

    float* w1t; cudaGetSymbolAddress((void**)&w1t, g_W1T);
    float* w2t; cudaGetSymbolAddress((void**)&w2t, g_W2T);

    {
        dim3 blk(32, 8);
        kT_transpose<<<dim3(D_IN / 32, D_EMB / 32), blk>>>(W1, w1t, D_EMB, D_IN);
        kT_transpose<<<dim3(D_EMB / 32, D_IN / 32), blk>>>(W2, w2t, D_IN, D_EMB);
    }
    k0_init<<<8, 256>>>(b1, bn1_beta);
    k1_precompute<<<K_CB / K1_ROWS, 256>>>(emb, W1, bn1_gamma, bn2_gamma, bn2_beta, b2);
    k1b_c<<<K_CB / 8, 256>>>(emb);
    cudaFuncSetAttribute(k2_wmma, cudaFuncAttributeMaxDynamicSharedMemorySize, K2W_SMEM);
    k2_wmma<<<T / MT, 256, K2W_SMEM>>>(inputs);
    k_exact<<<NB_EXACT, 256>>>(inputs, bn1_gamma, bn1_beta, b1, emb, S);
    k3_gather<<<8192, 256>>>(inputs, out + 1);
    k4_final<<<8, 256>>>(out, T);
}

// round 17
// speedup vs baseline: 1.6151x; 1.5285x over previous
#include <cuda_runtime.h>
#include <cuda_bf16.h>
#include <mma.h>
#include <math.h>
#include <stdint.h>

using namespace nvcuda;

#define D_IN   256
#define D_EMB  512
#define K_CB   2048
#define T_MAX  65536
#define MARGIN 1.4e-4f
#define NB_EXACT 2048

#define MT   128                 // tokens per CTA
#define FLD  264                 // bf16 pitch for token/A tiles
#define OLD  132                 // float pitch for output scan buffer
#define SZ_F (MT * FLD * 2)      // 67584 bytes
#define OFF_FLO (SZ_F)
#define OFF_A   (2 * SZ_F)
#define OFF_C   (3 * SZ_F)
#define K2W_SMEM (3 * SZ_F + K_CB * 4)   // 210944

// ---------------- scratch (device globals; no allocations allowed) -----------
__device__ __align__(16) float g_Q[K_CB * D_IN];
__device__ __align__(16) float g_W1T[D_IN * D_EMB];
__device__ __align__(16) float g_W2T[D_EMB * D_IN];
__device__ __align__(16) __nv_bfloat16 g_Ahi[K_CB * D_IN];  // [cb][i] row-major
__device__ __align__(16) __nv_bfloat16 g_Alo[K_CB * D_IN];
__device__ float g_c[K_CB];
__device__ float g_se[K_CB];
__device__ float g_b1eff[D_EMB];
__device__ int g_idx[T_MAX];
__device__ unsigned int g_hist[K_CB];
__device__ double g_partial[8192];
__device__ int g_ccount[T_MAX];
__device__ unsigned short g_cand[T_MAX][16];
__device__ int g_needy[T_MAX];
__device__ int g_nneedy;

static __device__ __forceinline__ uint32_t smem_u32(const void* p) {
    uint32_t a;
    asm("{ .reg .u64 t; cvta.to.shared.u64 t, %1; cvt.u32.u64 %0, t; }" : "=r"(a) : "l"(p));
    return a;
}
#define CP_COMMIT() asm volatile("cp.async.commit_group;" ::: "memory")
#define CP_WAIT(n)  asm volatile("cp.async.wait_group %0;" :: "n"(n) : "memory")

// ---------------- KT: tiled transpose ----------------------------------------
__global__ void kT_transpose(const float* __restrict__ src, float* __restrict__ dst,
                             int R, int C) {
    __shared__ float tile[32][33];
    int bx = blockIdx.x * 32, by = blockIdx.y * 32;
    int x = bx + threadIdx.x;
    int y = by + threadIdx.y;
#pragma unroll
    for (int j = 0; j < 32; j += 8)
        if (y + j < R && x < C) tile[threadIdx.y + j][threadIdx.x] = src[(size_t)(y + j) * C + x];
    __syncthreads();
    x = by + threadIdx.x;
    y = bx + threadIdx.y;
#pragma unroll
    for (int j = 0; j < 32; j += 8)
        if (y + j < C && x < R) dst[(size_t)(y + j) * R + x] = tile[threadIdx.x][threadIdx.y + j];
}

// ---------------- K0 -----------------------------------------------------------
__global__ void k0_init(const float* __restrict__ b1, const float* __restrict__ beta1) {
    int t = blockIdx.x * blockDim.x + threadIdx.x;
    if (t < D_EMB) {
        float s = b1[t];
        for (int i = 0; i < D_IN; i++) s = fmaf(beta1[i], g_W1T[(size_t)i * D_EMB + t], s);
        g_b1eff[t] = s;
    }
    if (t < K_CB) g_hist[t] = 0u;
    if (t == 0) g_nneedy = 0;
}

// ---------------- K1: precompute A (bf16 hi/lo split) and Q --------------------
#define K1_ROWS 8
#define EPAD 12
__global__ __launch_bounds__(256) void k1_precompute(
    const float* __restrict__ emb, const float* __restrict__ W1,
    const float* __restrict__ g1v, const float* __restrict__ g2v,
    const float* __restrict__ beta2, const float* __restrict__ b2) {
    __shared__ float sE[D_EMB * EPAD];
    __shared__ float sG2[D_EMB];
    __shared__ float sB2[D_EMB];
    const int t = threadIdx.x;
    const int k0 = blockIdx.x * K1_ROWS;
    const float bn_s = rsqrtf(1.0f + 1e-5f);

    {
        int r = t & 7, ov = t >> 3;
        for (int pass = 0; pass < 4; pass++) {
            int o4 = ov + pass * 32;
            float4 v = *(const float4*)&emb[(size_t)(k0 + r) * D_EMB + o4 * 4];
            sE[(o4 * 4 + 0) * EPAD + r] = v.x;
            sE[(o4 * 4 + 1) * EPAD + r] = v.y;
            sE[(o4 * 4 + 2) * EPAD + r] = v.z;
            sE[(o4 * 4 + 3) * EPAD + r] = v.w;
        }
    }
    for (int i = t; i < D_EMB; i += 256) {
        sG2[i] = g2v[i] * bn_s;
        sB2[i] = beta2[i];
    }
    __syncthreads();

    const int j = t;
    float accA[K1_ROWS], accQ[K1_ROWS];
    float qc = 0.f;
#pragma unroll
    for (int r = 0; r < K1_ROWS; r++) { accA[r] = 0.f; accQ[r] = 0.f; }

#pragma unroll 4
    for (int o = 0; o < D_EMB; o++) {
        float w1 = W1[(size_t)o * D_IN + j];
        float w2 = g_W2T[(size_t)o * D_IN + j];
        float gw = sG2[o] * w2;
        qc = fmaf(sB2[o], w2, qc);
        const float* e = &sE[o * EPAD];
        float4 e0 = *(const float4*)(e + 0);
        float4 e1 = *(const float4*)(e + 4);
        float ev[8] = {e0.x, e0.y, e0.z, e0.w, e1.x, e1.y, e1.z, e1.w};
#pragma unroll
        for (int r = 0; r < K1_ROWS; r++) {
            accA[r] = fmaf(ev[r], w1, accA[r]);
            accQ[r] = fmaf(ev[r], gw, accQ[r]);
        }
    }
    float g1j = g1v[j] * bn_s;
    float b2j = b2[j];
#pragma unroll
    for (int r = 0; r < K1_ROWS; r++) {
        float a = g1j * accA[r];
        __nv_bfloat16 hi = __float2bfloat16(a);
        __nv_bfloat16 lo = __float2bfloat16(a - __bfloat162float(hi));
        g_Ahi[(size_t)(k0 + r) * D_IN + j] = hi;
        g_Alo[(size_t)(k0 + r) * D_IN + j] = lo;
        g_Q[(size_t)(k0 + r) * D_IN + j] = accQ[r] + qc + b2j;
    }
}

// ---------------- K1b: c[k] and se[k] ------------------------------------------
__global__ __launch_bounds__(256) void k1b_c(const float* __restrict__ emb) {
    int w = blockIdx.x * 8 + (threadIdx.x >> 5);
    int lane = threadIdx.x & 31;
    if (w >= K_CB) return;
    float s = 0.f, se = 0.f;
    for (int o = lane; o < D_EMB; o += 32) {
        float ev = emb[(size_t)w * D_EMB + o];
        s = fmaf(ev, g_b1eff[o] - 0.5f * ev, s);
        se = __fadd_rn(se, __fmul_rn(ev, ev));
    }
#pragma unroll
    for (int d = 16; d >= 1; d >>= 1) {
        s += __shfl_xor_sync(0xffffffffu, s, d);
        se = __fadd_rn(se, __shfl_xor_sync(0xffffffffu, se, d));
    }
    if (lane == 0) { g_c[w] = s; g_se[w] = se; }
}

// ---------------- K2: wmma bf16 3-split GEMM, 16 warps, cp.async pipeline ------
// score = Fhi.Ahi + Flo.Ahi + Fhi.Alo + c   (identical math to the 1899us kernel)
__global__ __launch_bounds__(512, 1) void k2_wmma(const float* __restrict__ inputs) {
    extern __shared__ __align__(16) char smem[];
    __nv_bfloat16* sFhi = (__nv_bfloat16*)smem;
    __nv_bfloat16* sFlo = (__nv_bfloat16*)(smem + OFF_FLO);
    __nv_bfloat16* sA   = (__nv_bfloat16*)(smem + OFF_A);
    float* sOut = (float*)(smem + OFF_A);          // reuses A buffer
    float* sC   = (float*)(smem + OFF_C);
    const int tid = threadIdx.x;
    const int wid = tid >> 5;          // 0..15
    const int t0 = blockIdx.x * MT;
    const int tok0 = (wid & 3) * 32;   // 4 token groups of 32
    const int cb0l = (wid >> 2) * 32;  // 4 cb groups of 32
    const uint32_t sAu = smem_u32(sA);

    for (int i = tid; i < K_CB; i += 512) sC[i] = g_c[i];

    // stage tokens (bf16 hi/lo split, row-major [tok][FLD])
    for (int idx = tid; idx < MT * 64; idx += 512) {
        int tok = idx >> 6, q = idx & 63;
        float4 v = *(const float4*)&inputs[(size_t)(t0 + tok) * D_IN + q * 4];
        float f[4] = {v.x, v.y, v.z, v.w};
        uint32_t hp[2], lp[2];
#pragma unroll
        for (int pr = 0; pr < 2; pr++) {
            __nv_bfloat16 h0 = __float2bfloat16(f[pr * 2 + 0]);
            __nv_bfloat16 h1 = __float2bfloat16(f[pr * 2 + 1]);
            __nv_bfloat16 l0 = __float2bfloat16(f[pr * 2 + 0] - __bfloat162float(h0));
            __nv_bfloat16 l1 = __float2bfloat16(f[pr * 2 + 1] - __bfloat162float(h1));
            hp[pr] = (uint32_t)__bfloat16_as_ushort(h0) | ((uint32_t)__bfloat16_as_ushort(h1) << 16);
            lp[pr] = (uint32_t)__bfloat16_as_ushort(l0) | ((uint32_t)__bfloat16_as_ushort(l1) << 16);
        }
        *(uint2*)(sFhi + tok * FLD + q * 4) = make_uint2(hp[0], hp[1]);
        *(uint2*)(sFlo + tok * FLD + q * 4) = make_uint2(lp[0], lp[1]);
    }

    float v0 = -INFINITY, v1 = -INFINITY, v2 = -INFINITY;
    int i0 = 0, i1 = 0, i2 = 0;

    wmma::fragment<wmma::accumulator, 16, 16, 16, float> acc[2][2];

    // chunk = K-half (128 k = bytes [chunk*256, chunk*256+256) of each 528B row)
    auto copy_chunk = [&](const __nv_bfloat16* gbase, int chunk) {
        const char* src = (const char*)gbase;
#pragma unroll
        for (int z = 0; z < 4; z++) {
            int idx = tid + z * 512;            // 0..2047
            int r = idx >> 4, u = idx & 15;
            uint32_t d = sAu + (uint32_t)(r * (FLD * 2) + chunk * 256 + u * 16);
            const char* s = src + r * 512 + chunk * 256 + u * 16;
            asm volatile("cp.async.cg.shared.global [%0], [%1], 16;" :: "r"(d), "l"(s));
        }
    };
    auto mma_hi = [&](int chunk) {
#pragma unroll
        for (int ks = 0; ks < 8; ks++) {
            int k0 = (chunk * 8 + ks) * 16;
            wmma::fragment<wmma::matrix_a, 16, 16, 16, __nv_bfloat16, wmma::row_major> ah[2], al[2];
            wmma::fragment<wmma::matrix_b, 16, 16, 16, __nv_bfloat16, wmma::col_major> b[2];
#pragma unroll
            for (int mi = 0; mi < 2; mi++) {
                wmma::load_matrix_sync(ah[mi], sFhi + (tok0 + mi * 16) * FLD + k0, FLD);
                wmma::load_matrix_sync(al[mi], sFlo + (tok0 + mi * 16) * FLD + k0, FLD);
            }
#pragma unroll
            for (int ni = 0; ni < 2; ni++)
                wmma::load_matrix_sync(b[ni], sA + (cb0l + ni * 16) * FLD + k0, FLD);
#pragma unroll
            for (int ni = 0; ni < 2; ni++)
#pragma unroll
                for (int mi = 0; mi < 2; mi++) {
                    wmma::mma_sync(acc[mi][ni], ah[mi], b[ni], acc[mi][ni]);
                    wmma::mma_sync(acc[mi][ni], al[mi], b[ni], acc[mi][ni]);
                }
        }
    };
    auto mma_lo = [&](int chunk) {
#pragma unroll
        for (int ks = 0; ks < 8; ks++) {
            int k0 = (chunk * 8 + ks) * 16;
            wmma::fragment<wmma::matrix_a, 16, 16, 16, __nv_bfloat16, wmma::row_major> ah[2];
            wmma::fragment<wmma::matrix_b, 16, 16, 16, __nv_bfloat16, wmma::col_major> b[2];
#pragma unroll
            for (int mi = 0; mi < 2; mi++)
                wmma::load_matrix_sync(ah[mi], sFhi + (tok0 + mi * 16) * FLD + k0, FLD);
#pragma unroll
            for (int ni = 0; ni < 2; ni++)
                wmma::load_matrix_sync(b[ni], sA + (cb0l + ni * 16) * FLD + k0, FLD);
#pragma unroll
            for (int ni = 0; ni < 2; ni++)
#pragma unroll
                for (int mi = 0; mi < 2; mi++)
                    wmma::mma_sync(acc[mi][ni], ah[mi], b[ni], acc[mi][ni]);
        }
    };

    for (int ct = 0; ct < 16; ct++) {
        __syncthreads();                 // prev scan done (or token staging), sA free
        const __nv_bfloat16* baseHi = g_Ahi + (size_t)ct * 128 * D_IN;
        const __nv_bfloat16* baseLo = g_Alo + (size_t)ct * 128 * D_IN;
        copy_chunk(baseHi, 0); CP_COMMIT();      // g1
        copy_chunk(baseHi, 1); CP_COMMIT();      // g2
#pragma unroll
        for (int mi = 0; mi < 2; mi++)
#pragma unroll
            for (int ni = 0; ni < 2; ni++) wmma::fill_fragment(acc[mi][ni], 0.0f);
        CP_WAIT(1); __syncthreads();             // Hi0 ready
        mma_hi(0);
        __syncthreads();                          // chunk0 readers done
        copy_chunk(baseLo, 0); CP_COMMIT();      // g3 (overlaps mma_hi(1))
        CP_WAIT(1); __syncthreads();             // Hi1 ready
        mma_hi(1);
        __syncthreads();                          // chunk1 readers done
        copy_chunk(baseLo, 1); CP_COMMIT();      // g4 (overlaps mma_lo(0))
        CP_WAIT(1); __syncthreads();             // Lo0 ready
        mma_lo(0);
        CP_WAIT(0); __syncthreads();             // Lo1 ready
        mma_lo(1);
        __syncthreads();                          // all mma done; sA -> sOut
#pragma unroll
        for (int mi = 0; mi < 2; mi++)
#pragma unroll
            for (int ni = 0; ni < 2; ni++)
                wmma::store_matrix_sync(sOut + (tok0 + mi * 16) * OLD + cb0l + ni * 16,
                                        acc[mi][ni], OLD, wmma::mem_row_major);
        __syncthreads();
        {   // scan: 4 threads per token, 32 cb each, ascending index
            int tok = tid >> 2, q = tid & 3;
            const float* row = sOut + tok * OLD + q * 32;
            const float* cc = sC + ct * 128 + q * 32;
            int cbb = ct * 128 + q * 32;
#pragma unroll 4
            for (int j = 0; j < 32; j++) {
                float s = row[j] + cc[j];
                if (s > v2) {
                    int cb = cbb + j;
                    if (s > v1) {
                        if (s > v0) { v2 = v1; i2 = i1; v1 = v0; i1 = i0; v0 = s; i0 = cb; }
                        else        { v2 = v1; i2 = i1; v1 = s; i1 = cb; }
                    } else          { v2 = s; i2 = cb; }
                }
            }
        }
    }

    // merge the four quarter-scans of each token (value desc, index asc)
#pragma unroll
    for (int m = 1; m <= 2; m++) {
        float pv[3];
        int pi[3];
        pv[0] = __shfl_xor_sync(0xffffffffu, v0, m); pi[0] = __shfl_xor_sync(0xffffffffu, i0, m);
        pv[1] = __shfl_xor_sync(0xffffffffu, v1, m); pi[1] = __shfl_xor_sync(0xffffffffu, i1, m);
        pv[2] = __shfl_xor_sync(0xffffffffu, v2, m); pi[2] = __shfl_xor_sync(0xffffffffu, i2, m);
#pragma unroll
        for (int e = 0; e < 3; e++) {
            float s = pv[e]; int cb = pi[e];
            bool b0 = s > v0 || (s == v0 && cb < i0);
            bool b1 = s > v1 || (s == v1 && cb < i1);
            bool b2 = s > v2 || (s == v2 && cb < i2);
            if (b0) { v2 = v1; i2 = i1; v1 = v0; i1 = i0; v0 = s; i0 = cb; }
            else if (b1) { v2 = v1; i2 = i1; v1 = s; i1 = cb; }
            else if (b2) { v2 = s; i2 = cb; }
        }
    }
    if ((tid & 3) == 0) {
        int tok = t0 + (tid >> 2);
        float thr = v0 - MARGIN;
        if (v2 >= thr) {
            g_ccount[tok] = 17;
            int p = atomicAdd(&g_nneedy, 1);
            g_needy[p] = tok;
        } else if (v1 >= thr) {
            g_ccount[tok] = 2;
            g_cand[tok][0] = (unsigned short)i0;
            g_cand[tok][1] = (unsigned short)i1;
            int p = atomicAdd(&g_nneedy, 1);
            g_needy[p] = tok;
        } else {
            g_ccount[tok] = 1;
            g_idx[tok] = i0;
            atomicAdd(&g_hist[i0], 1u);
        }
    }
}

// ---------------- K_exact: jax-emulated fp32 distances, 4-token batches --------
__global__ __launch_bounds__(256) void k_exact(
    const float* __restrict__ inputs, const float* __restrict__ g1v,
    const float* __restrict__ beta1, const float* __restrict__ b1,
    const float* __restrict__ emb, float S) {
    __shared__ float sXin[4][D_IN];
    __shared__ float sX[4][D_EMB];
    __shared__ float sRed[256];
    __shared__ int sRedI[256];
    __shared__ float sSx[4];
    __shared__ int sTok[4];
    const int tid = threadIdx.x;
    const int n = g_nneedy;
    for (int base = blockIdx.x * 4; base < n; base += gridDim.x * 4) {
        int nb = n - base; if (nb > 4) nb = 4;
        if (tid < 4) sTok[tid] = g_needy[base + (tid < nb ? tid : 0)];
        __syncthreads();
        {
            float sc = __fmul_rn(g1v[tid], S);
            float bt = beta1[tid];
#pragma unroll
            for (int j = 0; j < 4; j++) {
                float f = inputs[(size_t)sTok[j] * D_IN + tid];
                sXin[j][tid] = __fadd_rn(__fmul_rn(f, sc), bt);
            }
        }
        __syncthreads();
        if (tid < 128) {
            int ob = tid * 4;
            float a[4][4];
#pragma unroll
            for (int j = 0; j < 4; j++)
#pragma unroll
                for (int c = 0; c < 4; c++) a[j][c] = 0.f;
#pragma unroll 4
            for (int i = 0; i < D_IN; i++) {
                float4 w = *(const float4*)(g_W1T + (size_t)i * D_EMB + ob);
#pragma unroll
                for (int j = 0; j < 4; j++) {
                    float xi = sXin[j][i];
                    a[j][0] = fmaf(xi, w.x, a[j][0]);
                    a[j][1] = fmaf(xi, w.y, a[j][1]);
                    a[j][2] = fmaf(xi, w.z, a[j][2]);
                    a[j][3] = fmaf(xi, w.w, a[j][3]);
                }
            }
#pragma unroll
            for (int j = 0; j < 4; j++) {
                sX[j][ob + 0] = __fadd_rn(a[j][0], b1[ob + 0]);
                sX[j][ob + 1] = __fadd_rn(a[j][1], b1[ob + 1]);
                sX[j][ob + 2] = __fadd_rn(a[j][2], b1[ob + 2]);
                sX[j][ob + 3] = __fadd_rn(a[j][3], b1[ob + 3]);
            }
        }
        __syncthreads();
        {
            float p[4];
#pragma unroll
            for (int j = 0; j < 4; j++)
                p[j] = __fadd_rn(__fmul_rn(sX[j][tid], sX[j][tid]),
                                 __fmul_rn(sX[j][tid + 256], sX[j][tid + 256]));
#pragma unroll
            for (int d = 16; d >= 1; d >>= 1)
#pragma unroll
                for (int j = 0; j < 4; j++)
                    p[j] = __fadd_rn(p[j], __shfl_xor_sync(0xffffffffu, p[j], d));
            if ((tid & 31) == 0)
#pragma unroll
                for (int j = 0; j < 4; j++) sRed[j * 8 + (tid >> 5)] = p[j];
            __syncthreads();
            if (tid < 4) {
                float s = 0.f;
#pragma unroll
                for (int w = 0; w < 8; w++) s = __fadd_rn(s, sRed[tid * 8 + w]);
                sSx[tid] = s;
            }
            __syncthreads();
        }
        for (int j = 0; j < nb; j++) {
            int t = sTok[j];
            float sx = sSx[j];
            int cnt = g_ccount[t];
            int C = (cnt <= 16) ? cnt : K_CB;
            float bd = INFINITY;
            int bk = 0x7fffffff;
            for (int ci = tid; ci < C; ci += 256) {
                int k = (cnt <= 16) ? (int)g_cand[t][ci] : ci;
                const float4* e4 = (const float4*)(emb + (size_t)k * D_EMB);
                float m = 0.f;
#pragma unroll 4
                for (int o4 = 0; o4 < D_EMB / 4; o4++) {
                    float4 e = e4[o4];
                    m = fmaf(sX[j][o4 * 4 + 0], e.x, m);
                    m = fmaf(sX[j][o4 * 4 + 1], e.y, m);
                    m = fmaf(sX[j][o4 * 4 + 2], e.z, m);
                    m = fmaf(sX[j][o4 * 4 + 3], e.w, m);
                }
                float d = __fsub_rn(__fadd_rn(sx, g_se[k]), __fmul_rn(2.0f, m));
                if (d < bd || (d == bd && k < bk)) { bd = d; bk = k; }
            }
            sRed[tid] = bd; sRedI[tid] = bk;
            __syncthreads();
            for (int d = 128; d >= 1; d >>= 1) {
                if (tid < d) {
                    float od = sRed[tid + d]; int ok = sRedI[tid + d];
                    if (od < sRed[tid] || (od == sRed[tid] && ok < sRedI[tid])) {
                        sRed[tid] = od; sRedI[tid] = ok;
                    }
                }
                __syncthreads();
            }
            if (tid == 0) { g_idx[t] = sRedI[0]; atomicAdd(&g_hist[sRedI[0]], 1u); }
            __syncthreads();
        }
    }
}

// ---------------- K3: gather + straight-through + SSE partials -----------------
__global__ __launch_bounds__(256) void k3_gather(const float* __restrict__ inputs,
                                                 float* __restrict__ outq) {
    const int t = threadIdx.x;
    float s = 0.f;
#pragma unroll
    for (int r = 0; r < 8; r++) {
        int gid = blockIdx.x * 2048 + r * 256 + t;
        int tok = gid >> 8;
        int j = gid & 255;
        int idx = g_idx[tok];
        float q = g_Q[(size_t)idx * D_IN + j];
        float x = inputs[gid];
        float d = __fsub_rn(q, x);
        outq[gid] = __fadd_rn(x, d);
        s = fmaf(d, d, s);
    }
#pragma unroll
    for (int d = 16; d >= 1; d >>= 1) s += __shfl_xor_sync(0xffffffffu, s, d);
    __shared__ float wsum[8];
    if ((t & 31) == 0) wsum[t >> 5] = s;
    __syncthreads();
    if (t == 0) {
        float tot = 0.f;
#pragma unroll
        for (int w = 0; w < 8; w++) tot += wsum[w];
        g_partial[blockIdx.x] = (double)tot;
    }
}

// ---------------- K4: loss + usage ---------------------------------------------
__global__ void k4_final(float* __restrict__ out, int T) {
    int t = blockIdx.x * 256 + threadIdx.x;
    if (t < K_CB) out[1 + (size_t)T * D_IN + t] = (float)g_hist[t] * (1.0f / (float)T);
    if (blockIdx.x == 0) {
        double s = 0.0;
        for (int i = threadIdx.x; i < 8192; i += 256) s += g_partial[i];
        __shared__ double sh[256];
        sh[threadIdx.x] = s;
        __syncthreads();
        for (int d = 128; d >= 1; d >>= 1) {
            if (threadIdx.x < d) sh[threadIdx.x] += sh[threadIdx.x + d];
            __syncthreads();
        }
        if (threadIdx.x == 0)
            out[0] = (float)(1.25 * sh[0] / ((double)T * (double)D_IN));
    }
}

// ---------------- launch --------------------------------------------------------
extern "C" void kernel_launch(void* const* d_in, const int* in_sizes, int n_in,
                              void* d_out, int out_size) {
    const float* inputs    = (const float*)d_in[0];
    const float* bn1_gamma = (const float*)d_in[1];
    const float* bn1_beta  = (const float*)d_in[2];
    const float* W1        = (const float*)d_in[3];
    const float* b1        = (const float*)d_in[4];
    const float* emb       = (const float*)d_in[5];
    const float* bn2_gamma = (const float*)d_in[6];
    const float* bn2_beta  = (const float*)d_in[7];
    const float* W2        = (const float*)d_in[8];
    const float* b2        = (const float*)d_in[9];
    float* out = (float*)d_out;
    const int T = in_sizes[0] / D_IN;   // 65536

    float af = (float)(1.0 + 1e-5);
    float S = 1.0f / sqrtf(af);

    float* w1t; cudaGetSymbolAddress((void**)&w1t, g_W1T);
    float* w2t; cudaGetSymbolAddress((void**)&w2t, g_W2T);

    {
        dim3 blk(32, 8);
        kT_transpose<<<dim3(D_IN / 32, D_EMB / 32), blk>>>(W1, w1t, D_EMB, D_IN);
        kT_transpose<<<dim3(D_EMB / 32, D_IN / 32), blk>>>(W2, w2t, D_IN, D_EMB);
    }
    k0_init<<<8, 256>>>(b1, bn1_beta);
    k1_precompute<<<K_CB / K1_ROWS, 256>>>(emb, W1, bn1_gamma, bn2_gamma, bn2_beta, b2);
    k1b_c<<<K_CB / 8, 256>>>(emb);
    cudaFuncSetAttribute(k2_wmma, cudaFuncAttributeMaxDynamicSharedMemorySize, K2W_SMEM);
    k2_wmma<<<T / MT, 512, K2W_SMEM>>>(inputs);
    k_exact<<<NB_EXACT, 256>>>(inputs, bn1_gamma, bn1_beta, b1, emb, S);
    k3_gather<<<8192, 256>>>(inputs, out + 1);
    k4_final<<<8, 256>>>(out, T);
}